// round 11
// baseline (speedup 1.0000x reference)
#include <cuda_runtime.h>

// RNN-T transducer loss. B=16, T=200, U=101, A=512, blank=0.
// LOG2-domain split lattice (exact; rel_err 0.0 in r7), barrier-free shfl
// schedule, 8x-unrolled wavefront (the ONLY change vs r7 — unroll is
// provably semantics-neutral in log domain: overrun steps hit frozen or
// ghost cells only, all row indices pre-clamped).
//   warp0 = alpha rows [0,ts), warp1 = beta rows [ts,Tb) reversed coords;
//   lane k owns columns {k,k+32,k+64,k+96}; neighbor via rotated shfl.
// Join: log_p = LSE_u(alpha[ts-1,u] + blk[ts-1,u] + beta[ts,u]).

#define BQ 16
#define TM 200
#define UM 101
#define AA 512
#define UP 104
#define NEG (-1.0e30f)
#define LOG2E 1.4426950408889634f
#define LN2   0.6931471805599453f
#define FULL  0xffffffffu

__device__ __align__(16) float g_blk[BQ][TM][UP];
__device__ __align__(16) float g_em [BQ][TM][UP];  // shifted: [t][u] = em[t][u-1]*log2e, [t][0]=0
__device__ float g_logp[BQ];
__device__ int   g_cnt = 0;

__global__ void tl_gather_kernel(const float* __restrict__ lp,
                                 const int*   __restrict__ labels)
{
    const int total  = BQ * TM * UM;
    const int stride = gridDim.x * blockDim.x;
    int i0 = blockIdx.x * blockDim.x + threadIdx.x;
    #pragma unroll
    for (int kk = 0; kk < 4; ++kk) {
        int i = i0 + kk * stride;
        if (i < total) {
            int u  = i % UM;
            int bt = i / UM;
            int t  = bt % TM;
            int b  = bt / TM;
            int lab = (u < UM - 1) ? __ldg(labels + b * (UM - 1) + u) : 0;
            size_t base = (size_t)i * AA;
            float bv = __ldg(lp + base);
            float ev = lab ? __ldg(lp + base + lab) : bv;
            g_blk[b][t][u]     = bv * LOG2E;
            g_em [b][t][u + 1] = ev * LOG2E;
            if (u == 0) g_em[b][t][0] = 0.0f;
            if (u == UM - 1) {
                g_blk[b][t][101] = 0.f; g_blk[b][t][102] = 0.f; g_blk[b][t][103] = 0.f;
                g_em [b][t][102] = 0.f; g_em [b][t][103] = 0.f;
            }
        }
    }
}

__device__ __forceinline__ float ex2(float x) { float y; asm("ex2.approx.f32 %0, %1;" : "=f"(y) : "f"(x)); return y; }
__device__ __forceinline__ float lg2(float x) { float y; asm("lg2.approx.f32 %0, %1;" : "=f"(y) : "f"(x)); return y; }

// log2(2^x + 2^y); exact pass-through when one arg is NEG (ex2(-huge)=0).
__device__ __forceinline__ float lae2(float x, float y)
{
    float m = fmaxf(x, y);
    float d = fminf(x, y) - m;
    return m + lg2(1.0f + ex2(d));
}

__global__ __launch_bounds__(256, 1)
void tl_lattice_kernel(const int* __restrict__ Tarr,
                       const int* __restrict__ Uarr,
                       float* __restrict__ out)
{
    extern __shared__ float sm[];
    float* s_blk = sm;                  // [TM][UP], log2 domain
    float* s_em  = sm + TM * UP;        // [TM][UP]
    __shared__ float s_ja[UP], s_jb[UP];

    const int b    = blockIdx.x;
    const int tid  = threadIdx.x;
    const int lane = tid & 31;
    const int wid  = tid >> 5;

    {   // stage blk/em (coalesced float4, 8 warps)
        const float4* gb = (const float4*)&g_blk[b][0][0];
        const float4* ge = (const float4*)&g_em [b][0][0];
        float4* sb = (float4*)s_blk;
        float4* se = (float4*)s_em;
        const int n4 = TM * UP / 4;     // 5200
        for (int k = tid; k < n4; k += 256) { sb[k] = gb[k]; se[k] = ge[k]; }
    }
    if (tid < UP) { s_ja[tid] = NEG; s_jb[tid] = 0.0f; }

    const int Tb  = __ldg(Tarr + b);
    const int Ub  = __ldg(Uarr + b);
    const int ts  = (Tb + 1) >> 1;      // forward owns rows [0,ts)
    const int nbk = Tb - ts;            // backward owns rows [ts,Tb)
    __syncthreads();

    const int src = (lane + 31) & 31;   // rotate-up source lane

    if (wid == 0) {
        // ---------------- forward: alpha over rows [0, ts) ----------------
        const int R = ts;
        const int nsteps = R + Ub;      // last cell (R-1, Ub) at step R-1+Ub
        float h[4] = {0.f, 0.f, 0.f, 0.f};

        for (int s0 = 0; s0 < nsteps; s0 += 8) {
            #pragma unroll
            for (int ds = 0; ds < 8; ++ds) {
                const int s = s0 + ds;
                float r0 = __shfl_sync(FULL, h[0], src);
                float r1 = __shfl_sync(FULL, h[1], src);
                float r2 = __shfl_sync(FULL, h[2], src);
                float r3 = __shfl_sync(FULL, h[3], src);
                float hin[4];
                hin[0] = lane ? r0 : NEG;
                hin[1] = lane ? r1 : r0;
                hin[2] = lane ? r2 : r1;
                hin[3] = lane ? r3 : r2;
                #pragma unroll
                for (int j = 0; j < 4; ++j) {
                    const int u  = lane + 32 * j;
                    const int t  = s - u;
                    const int tc = min(max(t, 0), R - 1);
                    const int uc = min(u, UP - 1);
                    const float emv  = s_em [ tc             * UP + uc];
                    const float blkv = s_blk[ max(tc - 1, 0) * UP + uc];
                    const float hor = hin[j] + emv;
                    const float ver = h[j]   + blkv;
                    const float lv  = lae2(ver, hor);
                    const float val = (t == 0) ? ((u == 0) ? 0.0f : hor) : lv;
                    h[j] = ((unsigned)t < (unsigned)R) ? val : h[j];
                }
            }
        }
        // junction row ts-1: ja[u] = alpha[ts-1,u] + blk[ts-1,u]
        #pragma unroll
        for (int j = 0; j < 4; ++j) {
            const int u = lane + 32 * j;
            if (u <= Ub) s_ja[u] = h[j] + s_blk[(R - 1) * UP + u];
        }
    } else if (wid == 1) {
        // ---------------- backward: beta over rows [ts, Tb) ----------------
        // coords: v = Ub-u, t' = Tb-1-t; beta'[t',v] mirrors the forward shape.
        const int R = nbk;
        const int nsteps = R + Ub;
        const float seedB = s_blk[(Tb - 1) * UP + Ub];
        float h[4] = {0.f, 0.f, 0.f, 0.f};

        for (int s0 = 0; s0 < nsteps; s0 += 8) {
            #pragma unroll
            for (int ds = 0; ds < 8; ++ds) {
                const int s = s0 + ds;
                float r0 = __shfl_sync(FULL, h[0], src);
                float r1 = __shfl_sync(FULL, h[1], src);
                float r2 = __shfl_sync(FULL, h[2], src);
                float r3 = __shfl_sync(FULL, h[3], src);
                float hin[4];
                hin[0] = lane ? r0 : NEG;
                hin[1] = lane ? r1 : r0;
                hin[2] = lane ? r2 : r1;
                hin[3] = lane ? r3 : r2;
                #pragma unroll
                for (int j = 0; j < 4; ++j) {
                    const int v   = lane + 32 * j;
                    const int tp  = s - v;
                    const int tpc = min(max(tp, 0), R - 1);
                    const int t   = Tb - 1 - tpc;            // real row
                    const int u   = Ub - v;
                    const int uc  = min(max(u, 0), UP - 1);
                    const float emv  = s_em [t * UP + min(uc + 1, UP - 1)]; // emit[t][u]
                    const float blkv = s_blk[t * UP + uc];                  // blk[t][u]
                    const float hor = hin[j] + emv;
                    const float ver = h[j]   + blkv;
                    const float lv  = lae2(ver, hor);
                    const float val = (tp == 0) ? ((v == 0) ? seedB : hor) : lv;
                    h[j] = ((unsigned)tp < (unsigned)R) ? val : h[j];
                }
            }
        }
        // junction row ts: jb[u] = beta[ts, u]
        #pragma unroll
        for (int j = 0; j < 4; ++j) {
            const int u = Ub - (lane + 32 * j);
            if (u >= 0) s_jb[u] = h[j];
        }
    }
    __syncthreads();

    // log_p = LN2 * LSE2_u(ja[u] + jb[u])   (warp 0)
    if (tid < 32) {
        float x0 = (tid      < UP) ? s_ja[tid]      + s_jb[tid]      : NEG;
        float x1 = (tid + 32 < UP) ? s_ja[tid + 32] + s_jb[tid + 32] : NEG;
        float x2 = (tid + 64 < UP) ? s_ja[tid + 64] + s_jb[tid + 64] : NEG;
        float x3 = (tid + 96 < UP) ? s_ja[tid + 96] + s_jb[tid + 96] : NEG;
        float m = fmaxf(fmaxf(x0, x1), fmaxf(x2, x3));
        #pragma unroll
        for (int o = 16; o > 0; o >>= 1)
            m = fmaxf(m, __shfl_xor_sync(FULL, m, o));
        float sum2 = ex2(x0 - m) + ex2(x1 - m) + ex2(x2 - m) + ex2(x3 - m);
        #pragma unroll
        for (int o = 16; o > 0; o >>= 1)
            sum2 += __shfl_xor_sync(FULL, sum2, o);
        if (tid == 0) g_logp[b] = (m + lg2(sum2)) * LN2;
    }
    __syncthreads();

    // fixed-order mean reduction in the last-arriving CTA (deterministic)
    if (tid == 0) {
        __threadfence();
        int old = atomicAdd(&g_cnt, 1);
        if (old == BQ - 1) {
            __threadfence();
            float ssum = 0.0f;
            #pragma unroll
            for (int i = 0; i < BQ; ++i) ssum += g_logp[i];
            out[0] = -ssum / (float)BQ;
            g_cnt = 0;                  // reset for next graph replay
        }
    }
}

extern "C" void kernel_launch(void* const* d_in, const int* in_sizes, int n_in,
                              void* d_out, int out_size)
{
    const float* lp     = (const float*)d_in[0];
    const int*   labels = (const int*)  d_in[1];
    const int*   Tarr   = (const int*)  d_in[2];
    const int*   Uarr   = (const int*)  d_in[3];
    float* out = (float*)d_out;

    const int smem_bytes = 2 * TM * UP * (int)sizeof(float);   // 166,400
    cudaFuncSetAttribute(tl_lattice_kernel,
                         cudaFuncAttributeMaxDynamicSharedMemorySize,
                         smem_bytes);

    const int total  = BQ * TM * UM;
    const int blocks = (total + 256 * 4 - 1) / (256 * 4);      // 316
    tl_gather_kernel<<<blocks, 256>>>(lp, labels);
    tl_lattice_kernel<<<BQ, 256, smem_bytes>>>(Tarr, Uarr, out);
}

// round 12
// speedup vs baseline: 1.0570x; 1.0570x over previous
#include <cuda_runtime.h>

// RNN-T transducer loss. B=16, T=200, U=101, A=512, blank=0.
// LOG2-domain split lattice (exact), barrier-free shfl schedule, 8x unroll.
// r12: float2-packed operand tables (1 LDS.64 per cell), NEG-init seeding
// (no per-cell boundary selects), single unsigned row clamp.
//   warp0 = alpha rows [0,ts), warp1 = beta rows [ts,Tb) in mirrored coords;
//   lane k owns columns {k,k+32,k+64,k+96}; neighbor via rotated shfl.
// Join: log_p = LSE_u(alpha[ts-1,u] + blk[ts-1,u] + beta[ts,u]).

#define BQ 16
#define TM 200
#define UM 101
#define AA 512
#define UP 104
#define HR 100           // max rows per half (ts<=100, nbk<=100)
#define NEG (-1.0e30f)
#define LOG2E 1.4426950408889634f
#define LN2   0.6931471805599453f
#define FULL  0xffffffffu

// Packed log2-domain tables (zero-initialized .bss; unwritten slots stay 0).
// g_pf[b][t][u] = (blk[t-1][u], emS[t][u])  for t in [0,ts)   (fwd half)
// g_pw[b][r][u] = (blk[ts+r][u], emit[ts+r][u]) for r in [0,nbk) (bwd half)
__device__ __align__(16) float2 g_pf[BQ][HR][UP];
__device__ __align__(16) float2 g_pw[BQ][HR][UP];
__device__ float g_jblk[BQ][UP];   // blk[ts-1][u]
__device__ float g_logp[BQ];
__device__ int   g_cnt = 0;

__device__ __forceinline__ float ex2(float x) { float y; asm("ex2.approx.f32 %0, %1;" : "=f"(y) : "f"(x)); return y; }
__device__ __forceinline__ float lg2(float x) { float y; asm("lg2.approx.f32 %0, %1;" : "=f"(y) : "f"(x)); return y; }

// log2(2^x + 2^y); exact pass-through when one arg is ~-1e30.
__device__ __forceinline__ float lae2(float x, float y)
{
    float m = fmaxf(x, y);
    float d = fminf(x, y) - m;
    return m + lg2(1.0f + ex2(d));
}

__global__ void tl_gather_kernel(const float* __restrict__ lp,
                                 const int*   __restrict__ labels,
                                 const int*   __restrict__ Tarr)
{
    const int total  = BQ * TM * UM;
    const int stride = gridDim.x * blockDim.x;
    int i0 = blockIdx.x * blockDim.x + threadIdx.x;
    #pragma unroll
    for (int kk = 0; kk < 4; ++kk) {
        int i = i0 + kk * stride;
        if (i < total) {
            int u  = i % UM;
            int bt = i / UM;
            int t  = bt % TM;
            int b  = bt / TM;
            int lab = (u < UM - 1) ? __ldg(labels + b * (UM - 1) + u) : 0;
            size_t base = (size_t)i * AA;
            float bv = __ldg(lp + base) * LOG2E;            // blk[t][u] (log2)
            float ev = lab ? __ldg(lp + base + lab) * LOG2E : bv;  // emit[t][u]
            int Tb = __ldg(Tarr + b);
            int ts = (Tb + 1) >> 1;
            if (t < ts) {
                if (t + 1 < ts) g_pf[b][t + 1][u].x = bv;   // blk[t][u] -> row t+1
                g_pf[b][t][u + 1].y = ev;                   // emS[t][u+1] = emit[t][u]
                if (t == ts - 1) g_jblk[b][u] = bv;
            } else if (t < Tb) {
                g_pw[b][t - ts][u] = make_float2(bv, ev);
            }
        }
    }
}

__global__ __launch_bounds__(256, 1)
void tl_lattice_kernel(const int* __restrict__ Tarr,
                       const int* __restrict__ Uarr,
                       float* __restrict__ out)
{
    extern __shared__ float sm[];
    float2* s_pf = (float2*)sm;              // [HR][UP] fwd pairs
    float2* s_pw = s_pf + HR * UP;           // [HR][UP] bwd pairs
    __shared__ float s_ja[UP], s_jb[UP];

    const int b    = blockIdx.x;
    const int tid  = threadIdx.x;
    const int lane = tid & 31;
    const int wid  = tid >> 5;

    {   // stage packed tables (coalesced float4, 8 warps)
        const float4* gf = (const float4*)&g_pf[b][0][0];
        const float4* gw = (const float4*)&g_pw[b][0][0];
        float4* sf = (float4*)s_pf;
        float4* sw = (float4*)s_pw;
        const int n4 = HR * UP / 2;          // 5200 float4 per half
        for (int k = tid; k < n4; k += 256) { sf[k] = gf[k]; sw[k] = gw[k]; }
    }
    if (tid < UP) { s_ja[tid] = NEG; s_jb[tid] = 0.0f; }

    const int Tb  = __ldg(Tarr + b);
    const int Ub  = __ldg(Uarr + b);
    const int ts  = (Tb + 1) >> 1;           // fwd rows [0,ts)
    const int nbk = Tb - ts;                 // bwd rows [ts,Tb)
    __syncthreads();

    const int src = (lane + 31) & 31;        // rotate-up source lane

    if (wid == 0) {
        // ---------------- forward: alpha over rows [0, ts) ----------------
        const int R = ts;
        const int nsteps = R + Ub;
        int uu[4], uc[4];
        float jb4[4];
        #pragma unroll
        for (int j = 0; j < 4; ++j) {
            uu[j] = lane + 32 * j;
            uc[j] = min(uu[j], UP - 1);
            jb4[j] = __ldg(&g_jblk[b][uc[j]]);   // prefetched junction blk row
        }
        float h[4] = {(lane == 0) ? 0.0f : NEG, NEG, NEG, NEG};

        for (int s0 = 1; s0 < nsteps; s0 += 8) {
            #pragma unroll
            for (int ds = 0; ds < 8; ++ds) {
                const int s = s0 + ds;
                float r0 = __shfl_sync(FULL, h[0], src);
                float r1 = __shfl_sync(FULL, h[1], src);
                float r2 = __shfl_sync(FULL, h[2], src);
                float r3 = __shfl_sync(FULL, h[3], src);
                float hin[4];
                hin[0] = lane ? r0 : NEG;
                hin[1] = lane ? r1 : r0;
                hin[2] = lane ? r2 : r1;
                hin[3] = lane ? r3 : r2;
                #pragma unroll
                for (int j = 0; j < 4; ++j) {
                    const int t  = s - uu[j];
                    const unsigned tc = min((unsigned)t, (unsigned)(R - 1)); // t<0 wraps -> R-1 (harmless)
                    const float2 pv = s_pf[tc * UP + uc[j]];
                    const float ver = h[j]   + pv.x;
                    const float hor = hin[j] + pv.y;
                    const float val = lae2(ver, hor);      // == hor exactly while h==NEG
                    h[j] = ((unsigned)t < (unsigned)R) ? val : h[j];
                }
            }
        }
        // junction row ts-1: ja[u] = alpha[ts-1,u] + blk[ts-1,u]
        #pragma unroll
        for (int j = 0; j < 4; ++j)
            if (uu[j] <= Ub) s_ja[uu[j]] = h[j] + jb4[j];
    } else if (wid == 1) {
        // ------------- backward: beta rows [ts,Tb), mirrored coords -------
        // tp = Tb-1-t, v = Ub-u;  pair row index r = t-ts = (nbk-1)-tp.
        const int R = nbk;
        const int nsteps = R + Ub;
        const float seedB = s_pw[(R - 1) * UP + Ub].x;     // blk[Tb-1][Ub]
        int vv[4], ucb[4];
        #pragma unroll
        for (int j = 0; j < 4; ++j) {
            vv[j]  = lane + 32 * j;
            ucb[j] = min(max(Ub - vv[j], 0), UP - 1);
        }
        float h[4] = {(lane == 0) ? seedB : NEG, NEG, NEG, NEG};

        for (int s0 = 1; s0 < nsteps; s0 += 8) {
            #pragma unroll
            for (int ds = 0; ds < 8; ++ds) {
                const int s = s0 + ds;
                float r0 = __shfl_sync(FULL, h[0], src);
                float r1 = __shfl_sync(FULL, h[1], src);
                float r2 = __shfl_sync(FULL, h[2], src);
                float r3 = __shfl_sync(FULL, h[3], src);
                float hin[4];
                hin[0] = lane ? r0 : NEG;
                hin[1] = lane ? r1 : r0;
                hin[2] = lane ? r2 : r1;
                hin[3] = lane ? r3 : r2;
                #pragma unroll
                for (int j = 0; j < 4; ++j) {
                    const int tp = s - vv[j];
                    const unsigned tpc = min((unsigned)tp, (unsigned)(R - 1));
                    const unsigned rb  = (unsigned)(R - 1) - tpc;
                    const float2 pv = s_pw[rb * UP + ucb[j]];
                    const float ver = h[j]   + pv.x;       // beta[t+1,u] + blk[t,u]
                    const float hor = hin[j] + pv.y;       // beta[t,u+1] + emit[t,u]
                    const float val = lae2(ver, hor);
                    h[j] = ((unsigned)tp < (unsigned)R) ? val : h[j];
                }
            }
        }
        // junction row ts: jb[u] = beta[ts, u]  (frozen at tp = R-1)
        #pragma unroll
        for (int j = 0; j < 4; ++j) {
            const int u = Ub - vv[j];
            if (u >= 0) s_jb[u] = h[j];
        }
    }
    __syncthreads();

    // log_p = LN2 * LSE2_u(ja[u] + jb[u])   (warp 0)
    if (tid < 32) {
        float x0 = (tid      < UP) ? s_ja[tid]      + s_jb[tid]      : NEG;
        float x1 = (tid + 32 < UP) ? s_ja[tid + 32] + s_jb[tid + 32] : NEG;
        float x2 = (tid + 64 < UP) ? s_ja[tid + 64] + s_jb[tid + 64] : NEG;
        float x3 = (tid + 96 < UP) ? s_ja[tid + 96] + s_jb[tid + 96] : NEG;
        float m = fmaxf(fmaxf(x0, x1), fmaxf(x2, x3));
        #pragma unroll
        for (int o = 16; o > 0; o >>= 1)
            m = fmaxf(m, __shfl_xor_sync(FULL, m, o));
        float sum2 = ex2(x0 - m) + ex2(x1 - m) + ex2(x2 - m) + ex2(x3 - m);
        #pragma unroll
        for (int o = 16; o > 0; o >>= 1)
            sum2 += __shfl_xor_sync(FULL, sum2, o);
        if (tid == 0) g_logp[b] = (m + lg2(sum2)) * LN2;
    }
    __syncthreads();

    // fixed-order mean reduction in the last-arriving CTA (deterministic)
    if (tid == 0) {
        __threadfence();
        int old = atomicAdd(&g_cnt, 1);
        if (old == BQ - 1) {
            __threadfence();
            float ssum = 0.0f;
            #pragma unroll
            for (int i = 0; i < BQ; ++i) ssum += g_logp[i];
            out[0] = -ssum / (float)BQ;
            g_cnt = 0;                       // reset for next graph replay
        }
    }
}

extern "C" void kernel_launch(void* const* d_in, const int* in_sizes, int n_in,
                              void* d_out, int out_size)
{
    const float* lp     = (const float*)d_in[0];
    const int*   labels = (const int*)  d_in[1];
    const int*   Tarr   = (const int*)  d_in[2];
    const int*   Uarr   = (const int*)  d_in[3];
    float* out = (float*)d_out;

    const int smem_bytes = 2 * HR * UP * (int)sizeof(float2);  // 166,400
    cudaFuncSetAttribute(tl_lattice_kernel,
                         cudaFuncAttributeMaxDynamicSharedMemorySize,
                         smem_bytes);

    const int total  = BQ * TM * UM;
    const int blocks = (total + 256 * 4 - 1) / (256 * 4);      // 316
    tl_gather_kernel<<<blocks, 256>>>(lp, labels, Tarr);
    tl_lattice_kernel<<<BQ, 256, smem_bytes>>>(Tarr, Uarr, out);
}